// round 6
// baseline (speedup 1.0000x reference)
#include <cuda_runtime.h>
#include <math.h>
#include <stdint.h>

#define HDIM 128
#define MAXN 50000
#define MAXE 640000
#define TM   128

// shared layout (floats)
#define SA_ST  260
#define WB_ST  36
#define WB_F   (TM * SA_ST)           // 33280
#define WB_SZ  (128 * WB_ST)          // 4608
#define B1_F   (WB_F + 2 * WB_SZ)
#define B2_F   (B1_F + 128)
#define W1L_F  (B2_F + 128)
#define DIST_F (W1L_F + 128)
#define REC_F  (DIST_F + TM)
#define SEND_F (REC_F + TM)
#define SMEM_FLOATS (SEND_F + TM)
#define SMEM_BYTES  (SMEM_FLOATS * 4)   // ~170 KB -> 1 CTA/SM

// ------------------------- device scratch -------------------------
__device__ __align__(16) float g_aggr[(size_t)MAXN * HDIM];
__device__ int   g_send[MAXE];
__device__ int   g_rec[MAXE];
__device__ float g_dist[MAXE];
__device__ __align__(16) float g_w1t[128 * 256];  // tf32-rounded, [n][k]
__device__ __align__(16) float g_w2t[128 * 128];  // tf32-rounded, [n][k]

// ------------------------- helpers -------------------------
__device__ __forceinline__ float silu_f(float v) {
    return __fdividef(v, 1.0f + __expf(-v));
}
__device__ __forceinline__ uint32_t tf32r(float f) {
    uint32_t r;
    asm("cvt.rna.tf32.f32 %0, %1;" : "=r"(r) : "f"(f));
    return r;
}
__device__ __forceinline__ uint32_t cvta_sh(const void* p) {
    uint32_t a;
    asm("{ .reg .u64 t; cvta.to.shared.u64 t, %1; cvt.u32.u64 %0, t; }"
        : "=r"(a) : "l"(p));
    return a;
}
__device__ __forceinline__ void mma8(float d[4], const uint32_t a[4],
                                     const uint32_t b[2]) {
    asm volatile(
        "mma.sync.aligned.m16n8k8.row.col.f32.tf32.tf32.f32 "
        "{%0,%1,%2,%3},{%4,%5,%6,%7},{%8,%9},{%0,%1,%2,%3};"
        : "+f"(d[0]), "+f"(d[1]), "+f"(d[2]), "+f"(d[3])
        : "r"(a[0]), "r"(a[1]), "r"(a[2]), "r"(a[3]), "r"(b[0]), "r"(b[1]));
}
__device__ __forceinline__ void red4(float* p, float a, float b, float c, float d) {
    asm volatile("red.global.add.v4.f32 [%0], {%1,%2,%3,%4};"
                 :: "l"(p), "f"(a), "f"(b), "f"(c), "f"(d) : "memory");
}
__device__ __forceinline__ void cp16(uint32_t dst_sh, const void* src) {
    asm volatile("cp.async.ca.shared.global [%0], [%1], 16;"
                 :: "r"(dst_sh), "l"(src) : "memory");
}
__device__ __forceinline__ void cp_commit() {
    asm volatile("cp.async.commit_group;" ::: "memory");
}
template <int W>
__device__ __forceinline__ void cp_wait() {
    asm volatile("cp.async.wait_group %0;" :: "n"(W) : "memory");
}

// ------------------------- prep kernels -------------------------
__global__ void zero_kernel(int n) {
    int i = blockIdx.x * blockDim.x + threadIdx.x;
    int st = gridDim.x * blockDim.x;
    for (; i < n; i += st) g_aggr[i] = 0.0f;
}

__global__ void prep_kernel(const int* __restrict__ ei32,
                            const float* __restrict__ pos, int N, int E) {
    bool is64 = true;
#pragma unroll
    for (int t = 0; t < 16; t++) is64 &= (ei32[2 * t + 1] == 0);
    int i = blockIdx.x * blockDim.x + threadIdx.x;
    int st = gridDim.x * blockDim.x;
    for (; i < E; i += st) {
        int s, r;
        if (is64) { s = ei32[2 * (size_t)i]; r = ei32[2 * ((size_t)E + i)]; }
        else      { s = ei32[i];             r = ei32[(size_t)E + i]; }
        s = min(max(s, 0), N - 1);
        r = min(max(r, 0), N - 1);
        g_send[i] = s;
        g_rec[i]  = r;
        float dx = pos[s * 3 + 0] - pos[r * 3 + 0];
        float dy = pos[s * 3 + 1] - pos[r * 3 + 1];
        float dz = pos[s * 3 + 2] - pos[r * 3 + 2];
        g_dist[i] = sqrtf(dx * dx + dy * dy + dz * dz);
    }
}

// transpose weights to [n][k] and pre-round to tf32
__global__ void wt_kernel(const float* __restrict__ w1, const float* __restrict__ w2) {
    int i = blockIdx.x * blockDim.x + threadIdx.x;
    int st = gridDim.x * blockDim.x;
    for (; i < 128 * 256 + 128 * 128; i += st) {
        if (i < 128 * 256) {
            int n = i >> 8, k = i & 255;
            g_w1t[i] = __uint_as_float(tf32r(w1[k * 128 + n]));
        } else {
            int j = i - 128 * 256;
            int n = j >> 7, k = j & 127;
            g_w2t[j] = __uint_as_float(tf32r(w2[k * 128 + n]));
        }
    }
}

// ------------------------- tiled tf32 mma GEMM (64x64 warp tiles) ------------
// Each of 4 warps computes a 64x64 output tile: mw = warp>>1, nw = warp&1.
__device__ __forceinline__ void issueB(const float* __restrict__ gB, int Kst,
                                       int c, int buf, uint32_t smbase, int tid) {
#pragma unroll
    for (int it = 0; it < 8; it++) {
        int idx = tid + it * 128;
        int n = idx >> 3, k4 = idx & 7;
        cp16(smbase + (WB_F + buf * WB_SZ + n * WB_ST + k4 * 4) * 4,
             gB + (size_t)n * Kst + c * 32 + k4 * 4);
    }
}

__device__ __forceinline__ void gemm_tc(const float* __restrict__ gB, int Kst,
                                        int nCh, float* sm, uint32_t smbase,
                                        int mw, int nw, int lane, int tid,
                                        float acc[4][8][4]) {
    issueB(gB, Kst, 0, 0, smbase, tid);
    cp_commit();
    for (int c = 0; c < nCh; c++) {
        if (c + 1 < nCh) {
            issueB(gB, Kst, c + 1, (c + 1) & 1, smbase, tid);
            cp_commit();
            cp_wait<1>();
        } else {
            cp_wait<0>();
        }
        __syncthreads();   // chunk c visible; also orders prior sA writes (first iter)
        const uint32_t* sAu = (const uint32_t*)sm;
        const uint32_t* wbu = (const uint32_t*)(sm + WB_F + (c & 1) * WB_SZ);
#pragma unroll
        for (int kk = 0; kk < 32; kk += 8) {
            int kc = c * 32 + kk + (lane & 3);
            uint32_t a[4][4], b[8][2];
#pragma unroll
            for (int mf = 0; mf < 4; mf++) {
                int r = mw * 64 + mf * 16 + (lane >> 2);
                a[mf][0] = sAu[r * SA_ST + kc];
                a[mf][1] = sAu[(r + 8) * SA_ST + kc];
                a[mf][2] = sAu[r * SA_ST + kc + 4];
                a[mf][3] = sAu[(r + 8) * SA_ST + kc + 4];
            }
#pragma unroll
            for (int nf = 0; nf < 8; nf++) {
                int n = nw * 64 + nf * 8 + (lane >> 2);
                b[nf][0] = wbu[n * WB_ST + kk + (lane & 3)];
                b[nf][1] = wbu[n * WB_ST + kk + (lane & 3) + 4];
            }
#pragma unroll
            for (int mf = 0; mf < 4; mf++)
#pragma unroll
                for (int nf = 0; nf < 8; nf++)
                    mma8(acc[mf][nf], a[mf], b[nf]);
        }
        __syncthreads();   // all reads of buf done before it is refilled / sA mutated
    }
}

// ------------------------- fused MLP kernel (edge / node) -------------------------
template <bool EDGE>
__global__ void __launch_bounds__(128, 1) mlp_mma_kernel(
    const float* __restrict__ x,
    const float* __restrict__ w1full,   // original w1 (dist row, edge only)
    const float* __restrict__ b1, const float* __restrict__ b2,
    float* __restrict__ out, int M) {
    extern __shared__ float sm[];
    const uint32_t smbase = cvta_sh(sm);
    const int tid  = threadIdx.x;
    const int lane = tid & 31;
    const int wid  = tid >> 5;
    const int mw   = wid >> 1;   // 0..1 (M half: 64 rows)
    const int nw   = wid & 1;    // 0..1 (N half: 64 cols)
    const int m0   = blockIdx.x * TM;

    if (tid < 128) {
        sm[B1_F + tid] = b1[tid];
        sm[B2_F + tid] = b2[tid];
        if (EDGE) sm[W1L_F + tid] = w1full[(size_t)256 * 128 + tid];
        if (EDGE) {
            int ge = m0 + tid;
            if (ge < M) {
                ((int*)sm)[SEND_F + tid] = g_send[ge];
                ((int*)sm)[REC_F + tid]  = g_rec[ge];
                sm[DIST_F + tid]         = g_dist[ge];
            } else {
                ((int*)sm)[SEND_F + tid] = 0;
                ((int*)sm)[REC_F + tid]  = -1;
                sm[DIST_F + tid]         = 0.0f;
            }
        }
    }
    __syncthreads();

    // gather state rows (tf32-rounded): cols 0..127 / 128..255
    const float4* x4 = (const float4*)x;
    const float4* a4 = (const float4*)g_aggr;
    for (int i = tid; i < TM * 32; i += 128) {
        int r = i >> 5, f = i & 31;
        float4 v0, v1;
        if (EDGE) {
            int s  = ((int*)sm)[SEND_F + r];
            int rc = ((int*)sm)[REC_F + r];
            if (rc < 0) rc = 0;
            v0 = x4[(size_t)s * 32 + f];
            v1 = x4[(size_t)rc * 32 + f];
        } else {
            int gn = m0 + r;
            if (gn >= M) gn = M - 1;
            v0 = x4[(size_t)gn * 32 + f];
            v1 = a4[(size_t)gn * 32 + f];
        }
        uint4 u0, u1;
        u0.x = tf32r(v0.x); u0.y = tf32r(v0.y); u0.z = tf32r(v0.z); u0.w = tf32r(v0.w);
        u1.x = tf32r(v1.x); u1.y = tf32r(v1.y); u1.z = tf32r(v1.z); u1.w = tf32r(v1.w);
        *(uint4*)&sm[r * SA_ST + f * 4]       = u0;
        *(uint4*)&sm[r * SA_ST + 128 + f * 4] = u1;
    }
    // (first gemm chunk's sync orders the gather for all warps)

    float acc[4][8][4];
#pragma unroll
    for (int mf = 0; mf < 4; mf++)
#pragma unroll
        for (int nf = 0; nf < 8; nf++)
#pragma unroll
            for (int g = 0; g < 4; g++) acc[mf][nf][g] = 0.0f;

    // GEMM1: K=256
    gemm_tc(g_w1t, 256, 8, sm, smbase, mw, nw, lane, tid, acc);

    // epilogue 1: h = silu(acc + b1 [+ dist*w1_last]) -> tf32 -> sA cols 0..127
#pragma unroll
    for (int mf = 0; mf < 4; mf++) {
        int r0 = mw * 64 + mf * 16 + (lane >> 2);
        int r1 = r0 + 8;
        float d0 = EDGE ? sm[DIST_F + r0] : 0.0f;
        float d1 = EDGE ? sm[DIST_F + r1] : 0.0f;
#pragma unroll
        for (int nf = 0; nf < 8; nf++) {
            int c0 = nw * 64 + nf * 8 + (lane & 3) * 2;
            float* v = acc[mf][nf];
            float wl0 = EDGE ? sm[W1L_F + c0] : 0.0f;
            float wl1 = EDGE ? sm[W1L_F + c0 + 1] : 0.0f;
            uint32_t h00 = tf32r(silu_f(v[0] + sm[B1_F + c0]     + d0 * wl0));
            uint32_t h01 = tf32r(silu_f(v[1] + sm[B1_F + c0 + 1] + d0 * wl1));
            uint32_t h10 = tf32r(silu_f(v[2] + sm[B1_F + c0]     + d1 * wl0));
            uint32_t h11 = tf32r(silu_f(v[3] + sm[B1_F + c0 + 1] + d1 * wl1));
            ((uint32_t*)sm)[r0 * SA_ST + c0]     = h00;
            ((uint32_t*)sm)[r0 * SA_ST + c0 + 1] = h01;
            ((uint32_t*)sm)[r1 * SA_ST + c0]     = h10;
            ((uint32_t*)sm)[r1 * SA_ST + c0 + 1] = h11;
            v[0] = v[1] = v[2] = v[3] = 0.0f;
        }
    }
    // (first GEMM2 chunk's sync orders these writes)

    // GEMM2: K=128
    gemm_tc(g_w2t, 128, 4, sm, smbase, mw, nw, lane, tid, acc);

    // epilogue 2: stage result (fp32) into sA cols 128..255
#pragma unroll
    for (int mf = 0; mf < 4; mf++) {
        int r0 = mw * 64 + mf * 16 + (lane >> 2);
        int r1 = r0 + 8;
#pragma unroll
        for (int nf = 0; nf < 8; nf++) {
            int c0 = nw * 64 + nf * 8 + (lane & 3) * 2;
            float* v = acc[mf][nf];
            float o00 = v[0] + sm[B2_F + c0];
            float o01 = v[1] + sm[B2_F + c0 + 1];
            float o10 = v[2] + sm[B2_F + c0];
            float o11 = v[3] + sm[B2_F + c0 + 1];
            if (EDGE) {
                o00 = silu_f(o00); o01 = silu_f(o01);
                o10 = silu_f(o10); o11 = silu_f(o11);
            }
            sm[r0 * SA_ST + 128 + c0]     = o00;
            sm[r0 * SA_ST + 128 + c0 + 1] = o01;
            sm[r1 * SA_ST + 128 + c0]     = o10;
            sm[r1 * SA_ST + 128 + c0 + 1] = o11;
        }
    }
    __syncthreads();

    // writeout: one row per thread (128 rows), scatter-add or store
    {
        int r = tid;
        const float4* src = (const float4*)&sm[r * SA_ST + 128];
        if (EDGE) {
            int rc = ((int*)sm)[REC_F + r];
            if (rc >= 0) {
                float* dst = &g_aggr[(size_t)rc * HDIM];
#pragma unroll
                for (int j = 0; j < 32; j++) {
                    float4 v = src[j];
                    red4(dst + j * 4, v.x, v.y, v.z, v.w);
                }
            }
        } else {
            int gn = m0 + r;
            if (gn < M) {
                float4* dst = (float4*)&out[(size_t)gn * HDIM];
#pragma unroll
                for (int j = 0; j < 32; j++) dst[j] = src[j];
            }
        }
    }
}

// ------------------------- launch -------------------------
extern "C" void kernel_launch(void* const* d_in, const int* in_sizes, int n_in,
                              void* d_out, int out_size) {
    const float* x   = (const float*)d_in[0];
    const float* pos = (const float*)d_in[1];
    const int*   ei  = (const int*)d_in[2];
    const float* mw1 = (const float*)d_in[3];
    const float* mb1 = (const float*)d_in[4];
    const float* mw2 = (const float*)d_in[5];
    const float* mb2 = (const float*)d_in[6];
    const float* uw1 = (const float*)d_in[7];
    const float* ub1 = (const float*)d_in[8];
    const float* uw2 = (const float*)d_in[9];
    const float* ub2 = (const float*)d_in[10];

    int N = in_sizes[0] / HDIM;
    int E = in_sizes[2] / 2;

    cudaFuncSetAttribute(mlp_mma_kernel<true>,
                         cudaFuncAttributeMaxDynamicSharedMemorySize, SMEM_BYTES);
    cudaFuncSetAttribute(mlp_mma_kernel<false>,
                         cudaFuncAttributeMaxDynamicSharedMemorySize, SMEM_BYTES);

    zero_kernel<<<256, 256>>>(N * HDIM);
    prep_kernel<<<512, 256>>>(ei, pos, N, E);
    wt_kernel<<<192, 256>>>(mw1, mw2);
    mlp_mma_kernel<true><<<(E + TM - 1) / TM, 128, SMEM_BYTES>>>(
        x, mw1, mb1, mb2, nullptr, E);
    wt_kernel<<<192, 256>>>(uw1, uw2);
    mlp_mma_kernel<false><<<(N + TM - 1) / TM, 128, SMEM_BYTES>>>(
        x, uw1, ub1, ub2, (float*)d_out, N);
}

// round 7
// speedup vs baseline: 1.2627x; 1.2627x over previous
#include <cuda_runtime.h>
#include <math.h>
#include <stdint.h>

#define HDIM 128
#define MAXN 50000
#define MAXE 640000
#define TM   64

// shared layout (floats)
#define SA_ST  260
#define WB_CH  4096                    // one 32k x 128n chunk, frag-ordered (16KB)
#define WB_F   (TM * SA_ST)            // 16640
#define B1_F   (WB_F + 2 * WB_CH)      // 24832
#define B2_F   (B1_F + 128)
#define W1L_F  (B2_F + 128)
#define DIST_F (W1L_F + 128)
#define REC_F  (DIST_F + TM)
#define SEND_F (REC_F + TM)
#define SMEM_FLOATS (SEND_F + TM)
#define SMEM_BYTES  (SMEM_FLOATS * 4)  // ~101.7 KB -> 2 CTAs/SM

// ------------------------- device scratch -------------------------
__device__ __align__(16) float g_aggr[(size_t)MAXN * HDIM];
__device__ int   g_send[MAXE];
__device__ int   g_rec[MAXE];
__device__ float g_dist[MAXE];
// frag-ordered tf32 weights: [kchunk][nb 16][kb 4][64 words]
__device__ __align__(16) float g_w1t[8 * WB_CH];
__device__ __align__(16) float g_w2t[4 * WB_CH];

// ------------------------- helpers -------------------------
__device__ __forceinline__ float silu_f(float v) {
    return __fdividef(v, 1.0f + __expf(-v));
}
__device__ __forceinline__ uint32_t tf32r(float f) {
    uint32_t r;
    asm("cvt.rna.tf32.f32 %0, %1;" : "=r"(r) : "f"(f));
    return r;
}
__device__ __forceinline__ uint32_t cvta_sh(const void* p) {
    uint32_t a;
    asm("{ .reg .u64 t; cvta.to.shared.u64 t, %1; cvt.u32.u64 %0, t; }"
        : "=r"(a) : "l"(p));
    return a;
}
__device__ __forceinline__ void mma8(float d[4], const uint32_t a[4],
                                     const uint32_t b[2]) {
    asm volatile(
        "mma.sync.aligned.m16n8k8.row.col.f32.tf32.tf32.f32 "
        "{%0,%1,%2,%3},{%4,%5,%6,%7},{%8,%9},{%0,%1,%2,%3};"
        : "+f"(d[0]), "+f"(d[1]), "+f"(d[2]), "+f"(d[3])
        : "r"(a[0]), "r"(a[1]), "r"(a[2]), "r"(a[3]), "r"(b[0]), "r"(b[1]));
}
__device__ __forceinline__ void red4(float* p, float a, float b, float c, float d) {
    asm volatile("red.global.add.v4.f32 [%0], {%1,%2,%3,%4};"
                 :: "l"(p), "f"(a), "f"(b), "f"(c), "f"(d) : "memory");
}
__device__ __forceinline__ void cp16(uint32_t dst_sh, const void* src) {
    asm volatile("cp.async.ca.shared.global [%0], [%1], 16;"
                 :: "r"(dst_sh), "l"(src) : "memory");
}
__device__ __forceinline__ void cp_commit() {
    asm volatile("cp.async.commit_group;" ::: "memory");
}
template <int W>
__device__ __forceinline__ void cp_wait() {
    asm volatile("cp.async.wait_group %0;" :: "n"(W) : "memory");
}

// ------------------------- prep kernels -------------------------
__global__ void zero_kernel(int n) {
    int i = blockIdx.x * blockDim.x + threadIdx.x;
    int st = gridDim.x * blockDim.x;
    for (; i < n; i += st) g_aggr[i] = 0.0f;
}

__global__ void prep_kernel(const int* __restrict__ ei32,
                            const float* __restrict__ pos, int N, int E) {
    bool is64 = true;
#pragma unroll
    for (int t = 0; t < 16; t++) is64 &= (ei32[2 * t + 1] == 0);
    int i = blockIdx.x * blockDim.x + threadIdx.x;
    int st = gridDim.x * blockDim.x;
    for (; i < E; i += st) {
        int s, r;
        if (is64) { s = ei32[2 * (size_t)i]; r = ei32[2 * ((size_t)E + i)]; }
        else      { s = ei32[i];             r = ei32[(size_t)E + i]; }
        s = min(max(s, 0), N - 1);
        r = min(max(r, 0), N - 1);
        g_send[i] = s;
        g_rec[i]  = r;
        float dx = pos[s * 3 + 0] - pos[r * 3 + 0];
        float dy = pos[s * 3 + 1] - pos[r * 3 + 1];
        float dz = pos[s * 3 + 2] - pos[r * 3 + 2];
        g_dist[i] = sqrtf(dx * dx + dy * dy + dz * dz);
    }
}

// frag-order index for B element (n, k):
//   chunk = k>>5, nb = n>>3, kb = (k>>3)&3, lane = (n&7)*4 + (k&3), reg = (k>>2)&1
__device__ __forceinline__ int fragidx(int n, int k) {
    return (k >> 5) * WB_CH + (n >> 3) * 256 + (((k >> 3) & 3) << 6) +
           (((n & 7) * 4 + (k & 3)) << 1) + ((k >> 2) & 1);
}

// transpose+permute weights to frag order, pre-round to tf32
__global__ void wt_kernel(const float* __restrict__ w1, const float* __restrict__ w2) {
    int i = blockIdx.x * blockDim.x + threadIdx.x;
    int st = gridDim.x * blockDim.x;
    for (; i < 128 * 256 + 128 * 128; i += st) {
        if (i < 128 * 256) {
            int n = i >> 8, k = i & 255;
            g_w1t[fragidx(n, k)] = __uint_as_float(tf32r(w1[k * 128 + n]));
        } else {
            int j = i - 128 * 256;
            int n = j >> 7, k = j & 127;
            g_w2t[fragidx(n, k)] = __uint_as_float(tf32r(w2[k * 128 + n]));
        }
    }
}

// ------------------------- tiled tf32 mma GEMM (32x64 warp tiles) ------------
__device__ __forceinline__ void issueB(const float* __restrict__ gB, int c,
                                       int buf, uint32_t smbase, int tid) {
#pragma unroll
    for (int it = 0; it < 8; it++) {
        int idx = (tid + it * 128) * 4;
        cp16(smbase + (WB_F + buf * WB_CH + idx) * 4, gB + c * WB_CH + idx);
    }
}

// acc[mf][nf][4]: warp tile rows mh*32..+31, cols nw*64..+63
__device__ __forceinline__ void gemm_tc(const float* __restrict__ gB, int nCh,
                                        float* sm, uint32_t smbase,
                                        int mh, int nw, int lane, int tid,
                                        float acc[2][8][4]) {
    issueB(gB, 0, 0, smbase, tid);
    cp_commit();
    for (int c = 0; c < nCh; c++) {
        if (c + 1 < nCh) {
            issueB(gB, c + 1, (c + 1) & 1, smbase, tid);
            cp_commit();
            cp_wait<1>();
        } else {
            cp_wait<0>();
        }
        __syncthreads();   // chunk c visible; also orders prior sA writes
        const uint32_t* sAu = (const uint32_t*)sm;
        const uint2*    wb2 = (const uint2*)(sm + WB_F + (c & 1) * WB_CH);
#pragma unroll
        for (int kb = 0; kb < 4; kb++) {
            int kc = c * 32 + kb * 8 + (lane & 3);
            uint32_t a[2][4];
            uint2    b[8];
#pragma unroll
            for (int mf = 0; mf < 2; mf++) {
                int r = mh * 32 + mf * 16 + (lane >> 2);
                a[mf][0] = sAu[r * SA_ST + kc];
                a[mf][1] = sAu[(r + 8) * SA_ST + kc];
                a[mf][2] = sAu[r * SA_ST + kc + 4];
                a[mf][3] = sAu[(r + 8) * SA_ST + kc + 4];
            }
#pragma unroll
            for (int nf = 0; nf < 8; nf++)
                b[nf] = wb2[(((nw * 8 + nf) << 2) + kb) * 32 + lane];
#pragma unroll
            for (int mf = 0; mf < 2; mf++)
#pragma unroll
                for (int nf = 0; nf < 8; nf++)
                    mma8(acc[mf][nf], a[mf], (const uint32_t*)&b[nf]);
        }
        __syncthreads();   // reads done before buf refill / sA mutation
    }
}

// ------------------------- fused MLP kernel (edge / node) -------------------------
template <bool EDGE>
__global__ void __launch_bounds__(128, 2) mlp_mma_kernel(
    const float* __restrict__ x,
    const float* __restrict__ w1full,   // original w1 (dist row, edge only)
    const float* __restrict__ b1, const float* __restrict__ b2,
    float* __restrict__ out, int M) {
    extern __shared__ float sm[];
    const uint32_t smbase = cvta_sh(sm);
    const int tid  = threadIdx.x;
    const int lane = tid & 31;
    const int wid  = tid >> 5;
    const int mh   = wid >> 1;   // 0..1 (32-row block)
    const int nw   = wid & 1;    // 0..1 (64-col block)
    const int m0   = blockIdx.x * TM;

    if (tid < 128) {
        sm[B1_F + tid] = b1[tid];
        sm[B2_F + tid] = b2[tid];
        if (EDGE) sm[W1L_F + tid] = w1full[(size_t)256 * 128 + tid];
    }
    if (EDGE && tid < TM) {
        int ge = m0 + tid;
        if (ge < M) {
            ((int*)sm)[SEND_F + tid] = g_send[ge];
            ((int*)sm)[REC_F + tid]  = g_rec[ge];
            sm[DIST_F + tid]         = g_dist[ge];
        } else {
            ((int*)sm)[SEND_F + tid] = 0;
            ((int*)sm)[REC_F + tid]  = -1;
            sm[DIST_F + tid]         = 0.0f;
        }
    }
    __syncthreads();

    // gather state rows (tf32-rounded): cols 0..127 / 128..255
    const float4* x4 = (const float4*)x;
    const float4* a4 = (const float4*)g_aggr;
    for (int i = tid; i < TM * 32; i += 128) {
        int r = i >> 5, f = i & 31;
        float4 v0, v1;
        if (EDGE) {
            int s  = ((int*)sm)[SEND_F + r];
            int rc = ((int*)sm)[REC_F + r];
            if (rc < 0) rc = 0;
            v0 = x4[(size_t)s * 32 + f];
            v1 = x4[(size_t)rc * 32 + f];
        } else {
            int gn = m0 + r;
            if (gn >= M) gn = M - 1;
            v0 = x4[(size_t)gn * 32 + f];
            v1 = a4[(size_t)gn * 32 + f];
        }
        uint4 u0, u1;
        u0.x = tf32r(v0.x); u0.y = tf32r(v0.y); u0.z = tf32r(v0.z); u0.w = tf32r(v0.w);
        u1.x = tf32r(v1.x); u1.y = tf32r(v1.y); u1.z = tf32r(v1.z); u1.w = tf32r(v1.w);
        *(uint4*)&sm[r * SA_ST + f * 4]       = u0;
        *(uint4*)&sm[r * SA_ST + 128 + f * 4] = u1;
    }
    // (first gemm chunk's sync orders the gather)

    float acc[2][8][4];
#pragma unroll
    for (int mf = 0; mf < 2; mf++)
#pragma unroll
        for (int nf = 0; nf < 8; nf++)
#pragma unroll
            for (int g = 0; g < 4; g++) acc[mf][nf][g] = 0.0f;

    // GEMM1: K=256 (8 chunks)
    gemm_tc(g_w1t, 8, sm, smbase, mh, nw, lane, tid, acc);

    // epilogue 1: h = silu(acc + b1 [+ dist*w1_last]) -> tf32 -> sA cols 0..127
#pragma unroll
    for (int mf = 0; mf < 2; mf++) {
        int r0 = mh * 32 + mf * 16 + (lane >> 2);
        int r1 = r0 + 8;
        float d0 = EDGE ? sm[DIST_F + r0] : 0.0f;
        float d1 = EDGE ? sm[DIST_F + r1] : 0.0f;
#pragma unroll
        for (int nf = 0; nf < 8; nf++) {
            int c0 = nw * 64 + nf * 8 + (lane & 3) * 2;
            float* v = acc[mf][nf];
            float wl0 = EDGE ? sm[W1L_F + c0] : 0.0f;
            float wl1 = EDGE ? sm[W1L_F + c0 + 1] : 0.0f;
            uint32_t h00 = tf32r(silu_f(v[0] + sm[B1_F + c0]     + d0 * wl0));
            uint32_t h01 = tf32r(silu_f(v[1] + sm[B1_F + c0 + 1] + d0 * wl1));
            uint32_t h10 = tf32r(silu_f(v[2] + sm[B1_F + c0]     + d1 * wl0));
            uint32_t h11 = tf32r(silu_f(v[3] + sm[B1_F + c0 + 1] + d1 * wl1));
            ((uint32_t*)sm)[r0 * SA_ST + c0]     = h00;
            ((uint32_t*)sm)[r0 * SA_ST + c0 + 1] = h01;
            ((uint32_t*)sm)[r1 * SA_ST + c0]     = h10;
            ((uint32_t*)sm)[r1 * SA_ST + c0 + 1] = h11;
            v[0] = v[1] = v[2] = v[3] = 0.0f;
        }
    }
    // (first GEMM2 chunk's sync orders these writes)

    // GEMM2: K=128 (4 chunks)
    gemm_tc(g_w2t, 4, sm, smbase, mh, nw, lane, tid, acc);

    // epilogue 2: stage result (fp32) into sA cols 128..255
#pragma unroll
    for (int mf = 0; mf < 2; mf++) {
        int r0 = mh * 32 + mf * 16 + (lane >> 2);
        int r1 = r0 + 8;
#pragma unroll
        for (int nf = 0; nf < 8; nf++) {
            int c0 = nw * 64 + nf * 8 + (lane & 3) * 2;
            float* v = acc[mf][nf];
            float o00 = v[0] + sm[B2_F + c0];
            float o01 = v[1] + sm[B2_F + c0 + 1];
            float o10 = v[2] + sm[B2_F + c0];
            float o11 = v[3] + sm[B2_F + c0 + 1];
            if (EDGE) {
                o00 = silu_f(o00); o01 = silu_f(o01);
                o10 = silu_f(o10); o11 = silu_f(o11);
            }
            sm[r0 * SA_ST + 128 + c0]     = o00;
            sm[r0 * SA_ST + 128 + c0 + 1] = o01;
            sm[r1 * SA_ST + 128 + c0]     = o10;
            sm[r1 * SA_ST + 128 + c0 + 1] = o11;
        }
    }
    __syncthreads();

    // writeout: 64 rows x 2 halves, scatter-add or store
    {
        int r = tid >> 1, half = tid & 1;
        const float4* src = (const float4*)&sm[r * SA_ST + 128 + half * 64];
        if (EDGE) {
            int rc = ((int*)sm)[REC_F + r];
            if (rc >= 0) {
                float* dst = &g_aggr[(size_t)rc * HDIM + half * 64];
#pragma unroll
                for (int j = 0; j < 16; j++) {
                    float4 v = src[j];
                    red4(dst + j * 4, v.x, v.y, v.z, v.w);
                }
            }
        } else {
            int gn = m0 + r;
            if (gn < M) {
                float4* dst = (float4*)&out[(size_t)gn * HDIM + half * 64];
#pragma unroll
                for (int j = 0; j < 16; j++) dst[j] = src[j];
            }
        }
    }
}

// ------------------------- launch -------------------------
extern "C" void kernel_launch(void* const* d_in, const int* in_sizes, int n_in,
                              void* d_out, int out_size) {
    const float* x   = (const float*)d_in[0];
    const float* pos = (const float*)d_in[1];
    const int*   ei  = (const int*)d_in[2];
    const float* mw1 = (const float*)d_in[3];
    const float* mb1 = (const float*)d_in[4];
    const float* mw2 = (const float*)d_in[5];
    const float* mb2 = (const float*)d_in[6];
    const float* uw1 = (const float*)d_in[7];
    const float* ub1 = (const float*)d_in[8];
    const float* uw2 = (const float*)d_in[9];
    const float* ub2 = (const float*)d_in[10];

    int N = in_sizes[0] / HDIM;
    int E = in_sizes[2] / 2;

    cudaFuncSetAttribute(mlp_mma_kernel<true>,
                         cudaFuncAttributeMaxDynamicSharedMemorySize, SMEM_BYTES);
    cudaFuncSetAttribute(mlp_mma_kernel<false>,
                         cudaFuncAttributeMaxDynamicSharedMemorySize, SMEM_BYTES);

    zero_kernel<<<256, 256>>>(N * HDIM);
    prep_kernel<<<512, 256>>>(ei, pos, N, E);
    wt_kernel<<<192, 256>>>(mw1, mw2);
    mlp_mma_kernel<true><<<(E + TM - 1) / TM, 128, SMEM_BYTES>>>(
        x, mw1, mb1, mb2, nullptr, E);
    wt_kernel<<<192, 256>>>(uw1, uw2);
    mlp_mma_kernel<false><<<(N + TM - 1) / TM, 128, SMEM_BYTES>>>(
        x, uw1, ub1, ub2, (float*)d_out, N);
}

// round 9
// speedup vs baseline: 2.1398x; 1.6946x over previous
#include <cuda_runtime.h>
#include <cuda_fp16.h>
#include <math.h>
#include <stdint.h>

#define HDIM 128
#define MAXN 50000
#define MAXE 640000
#define TMR  128                    // rows per CTA tile

// byte-offset shared layout
#define APB     528                 // A row pitch bytes (264 halves)
#define WB_B    (TMR * APB)         // 67584
#define WB_CHB  16384               // one 64k x 128n fp16 chunk, frag-ordered
#define B1_B    (WB_B + 2 * WB_CHB) // 100352
#define B2_B    (B1_B + 512)
#define W1L_B   (B2_B + 512)
#define DIST_B  (W1L_B + 512)
#define REC_B   (DIST_B + 512)
#define SEND_B  (REC_B + 512)
#define SMEM_BYTES (SEND_B + 512)   // 103424 -> 2 CTAs/SM

// ------------------------- device scratch -------------------------
__device__ __align__(16) float g_aggr[(size_t)MAXN * HDIM];
__device__ int   g_send[MAXE];
__device__ int   g_rec[MAXE];
__device__ float g_dist[MAXE];
// frag-ordered fp16 weights: [kchunk64][nb*4+ks][lane][reg] packed as halves
__device__ __align__(16) __half g_w1h[4 * 8192];   // K=256: 4 chunks
__device__ __align__(16) __half g_w2h[2 * 8192];   // K=128: 2 chunks

// ------------------------- helpers -------------------------
__device__ __forceinline__ float silu_f(float v) {
    return __fdividef(v, 1.0f + __expf(-v));
}
__device__ __forceinline__ uint32_t cvta_sh(const void* p) {
    uint32_t a;
    asm("{ .reg .u64 t; cvta.to.shared.u64 t, %1; cvt.u32.u64 %0, t; }"
        : "=r"(a) : "l"(p));
    return a;
}
__device__ __forceinline__ void mma16(float d[4], const uint32_t a[4],
                                      const uint32_t b[2]) {
    asm volatile(
        "mma.sync.aligned.m16n8k16.row.col.f32.f16.f16.f32 "
        "{%0,%1,%2,%3},{%4,%5,%6,%7},{%8,%9},{%0,%1,%2,%3};"
        : "+f"(d[0]), "+f"(d[1]), "+f"(d[2]), "+f"(d[3])
        : "r"(a[0]), "r"(a[1]), "r"(a[2]), "r"(a[3]), "r"(b[0]), "r"(b[1]));
}
__device__ __forceinline__ void red4(float* p, float a, float b, float c, float d) {
    asm volatile("red.global.add.v4.f32 [%0], {%1,%2,%3,%4};"
                 :: "l"(p), "f"(a), "f"(b), "f"(c), "f"(d) : "memory");
}
__device__ __forceinline__ void cp16(uint32_t dst_sh, const void* src) {
    asm volatile("cp.async.ca.shared.global [%0], [%1], 16;"
                 :: "r"(dst_sh), "l"(src) : "memory");
}
__device__ __forceinline__ void cp_commit() {
    asm volatile("cp.async.commit_group;" ::: "memory");
}
template <int W>
__device__ __forceinline__ void cp_wait() {
    asm volatile("cp.async.wait_group %0;" :: "n"(W) : "memory");
}

// ------------------------- prep kernels -------------------------
__global__ void zero_kernel(int n) {
    int i = blockIdx.x * blockDim.x + threadIdx.x;
    int st = gridDim.x * blockDim.x;
    for (; i < n; i += st) g_aggr[i] = 0.0f;
}

__global__ void prep_kernel(const int* __restrict__ ei32,
                            const float* __restrict__ pos, int N, int E) {
    bool is64 = true;
#pragma unroll
    for (int t = 0; t < 16; t++) is64 &= (ei32[2 * t + 1] == 0);
    int i = blockIdx.x * blockDim.x + threadIdx.x;
    int st = gridDim.x * blockDim.x;
    for (; i < E; i += st) {
        int s, r;
        if (is64) { s = ei32[2 * (size_t)i]; r = ei32[2 * ((size_t)E + i)]; }
        else      { s = ei32[i];             r = ei32[(size_t)E + i]; }
        s = min(max(s, 0), N - 1);
        r = min(max(r, 0), N - 1);
        g_send[i] = s;
        g_rec[i]  = r;
        float dx = pos[s * 3 + 0] - pos[r * 3 + 0];
        float dy = pos[s * 3 + 1] - pos[r * 3 + 1];
        float dz = pos[s * 3 + 2] - pos[r * 3 + 2];
        g_dist[i] = sqrtf(dx * dx + dy * dy + dz * dz);
    }
}

// frag-order half-index for weight element (n, k), 64k-chunks.
// Matches the LDS.64 per-lane load: word = chunkbase + (nb*4+ks)*64 + lane*2 + reg
__device__ __forceinline__ int fragh(int n, int k) {
    int kc   = k >> 6;
    int ks   = (k >> 4) & 3;
    int reg  = (k >> 3) & 1;
    int lane = (n & 7) * 4 + ((k >> 1) & 3);
    int idx32 = kc * 4096 + (((n >> 3) * 4 + ks) << 6) + lane * 2 + reg;
    return idx32 * 2 + (k & 1);
}

// transpose+permute weights to fp16 frag order
__global__ void wt_kernel(const float* __restrict__ w1, const float* __restrict__ w2) {
    int i = blockIdx.x * blockDim.x + threadIdx.x;
    int st = gridDim.x * blockDim.x;
    for (; i < 128 * 256 + 128 * 128; i += st) {
        if (i < 128 * 256) {
            int n = i >> 8, k = i & 255;
            g_w1h[fragh(n, k)] = __float2half_rn(w1[k * 128 + n]);
        } else {
            int j = i - 128 * 256;
            int n = j >> 7, k = j & 127;
            g_w2h[fragh(n, k)] = __float2half_rn(w2[k * 128 + n]);
        }
    }
}

// ------------------------- fp16 mma GEMM (32x64 warp tiles, 8 warps) ---------
__device__ __forceinline__ void issueB(const __half* __restrict__ gB, int c,
                                       int buf, uint32_t smbase, int tid) {
#pragma unroll
    for (int it = 0; it < 4; it++) {
        int idx = (tid + it * 256) * 16;
        cp16(smbase + WB_B + buf * WB_CHB + idx, (const char*)gB + c * WB_CHB + idx);
    }
}

__device__ __forceinline__ void gemm_fp16(const __half* __restrict__ gB, int nCh,
                                          char* smc, uint32_t smbase,
                                          int mw, int nw, int lane, int tid,
                                          float acc[2][8][4]) {
    issueB(gB, 0, 0, smbase, tid);
    cp_commit();
    for (int c = 0; c < nCh; c++) {
        if (c + 1 < nCh) {
            issueB(gB, c + 1, (c + 1) & 1, smbase, tid);
            cp_commit();
            cp_wait<1>();
        } else {
            cp_wait<0>();
        }
        __syncthreads();   // chunk c visible; orders prior sA writes
        const char* wb = smc + WB_B + (c & 1) * WB_CHB;
#pragma unroll
        for (int ks = 0; ks < 4; ks++) {
            int kb = c * 64 + ks * 16 + (lane & 3) * 2;   // half index
            uint32_t a[2][4];
            uint2    b[8];
#pragma unroll
            for (int mf = 0; mf < 2; mf++) {
                int r = mw * 32 + mf * 16 + (lane >> 2);
                const char* base = smc + r * APB + kb * 2;
                a[mf][0] = *(const uint32_t*)base;
                a[mf][1] = *(const uint32_t*)(base + 8 * APB);
                a[mf][2] = *(const uint32_t*)(base + 16);
                a[mf][3] = *(const uint32_t*)(base + 8 * APB + 16);
            }
#pragma unroll
            for (int nf = 0; nf < 8; nf++) {
                int nb = nw * 8 + nf;
                b[nf] = *(const uint2*)(wb + (((nb * 4 + ks) << 5) + lane) * 8);
            }
#pragma unroll
            for (int mf = 0; mf < 2; mf++)
#pragma unroll
                for (int nf = 0; nf < 8; nf++)
                    mma16(acc[mf][nf], a[mf], (const uint32_t*)&b[nf]);
        }
        __syncthreads();   // reads done before buf refill / sA mutation
    }
}

// ------------------------- fused MLP kernel (edge / node) -------------------------
template <bool EDGE>
__global__ void __launch_bounds__(256, 2) mlp_mma_kernel(
    const float* __restrict__ x,
    const float* __restrict__ w1full,   // original w1 (dist row, edge only)
    const float* __restrict__ b1, const float* __restrict__ b2,
    float* __restrict__ out, int M) {
    extern __shared__ char smc[];
    const uint32_t smbase = cvta_sh(smc);
    float* sB1  = (float*)(smc + B1_B);
    float* sB2  = (float*)(smc + B2_B);
    float* sW1l = (float*)(smc + W1L_B);
    float* sDst = (float*)(smc + DIST_B);
    int*   sRec = (int*)(smc + REC_B);
    int*   sSnd = (int*)(smc + SEND_B);

    const int tid  = threadIdx.x;
    const int lane = tid & 31;
    const int wid  = tid >> 5;
    const int mw   = wid >> 1;   // 0..3 (32-row block)
    const int nw   = wid & 1;    // 0..1 (64-col block)
    const int m0   = blockIdx.x * TMR;

    if (tid < 128) {
        sB1[tid] = b1[tid];
        sB2[tid] = b2[tid];
        if (EDGE) {
            sW1l[tid] = w1full[(size_t)256 * 128 + tid];
            int ge = m0 + tid;
            if (ge < M) {
                sSnd[tid] = g_send[ge];
                sRec[tid] = g_rec[ge];
                sDst[tid] = g_dist[ge];
            } else {
                sSnd[tid] = 0; sRec[tid] = -1; sDst[tid] = 0.0f;
            }
        }
    }
    __syncthreads();

    // gather state rows -> fp16: cols 0..127 (send/x) / 128..255 (rec/aggr)
    const float4* x4 = (const float4*)x;
    const float4* a4 = (const float4*)g_aggr;
    for (int i = tid; i < TMR * 32; i += 256) {
        int r = i >> 5, f = i & 31;
        float4 v0, v1;
        if (EDGE) {
            int s  = sSnd[r];
            int rc = sRec[r];
            if (rc < 0) rc = 0;
            v0 = x4[(size_t)s * 32 + f];
            v1 = x4[(size_t)rc * 32 + f];
        } else {
            int gn = m0 + r;
            if (gn >= M) gn = M - 1;
            v0 = x4[(size_t)gn * 32 + f];
            v1 = a4[(size_t)gn * 32 + f];
        }
        uint2 u0, u1;
        ((half2*)&u0)[0] = __floats2half2_rn(v0.x, v0.y);
        ((half2*)&u0)[1] = __floats2half2_rn(v0.z, v0.w);
        ((half2*)&u1)[0] = __floats2half2_rn(v1.x, v1.y);
        ((half2*)&u1)[1] = __floats2half2_rn(v1.z, v1.w);
        *(uint2*)(smc + r * APB + f * 8)       = u0;
        *(uint2*)(smc + r * APB + 256 + f * 8) = u1;
    }
    // (first gemm chunk's sync orders the gather)

    float acc[2][8][4];
#pragma unroll
    for (int mf = 0; mf < 2; mf++)
#pragma unroll
        for (int nf = 0; nf < 8; nf++)
#pragma unroll
            for (int g = 0; g < 4; g++) acc[mf][nf][g] = 0.0f;

    // GEMM1: K=256 (4 chunks of 64)
    gemm_fp16(g_w1h, 4, smc, smbase, mw, nw, lane, tid, acc);

    // epilogue 1: h = silu(acc + b1 [+ dist*w1_last]) -> fp16 -> A cols 0..127
#pragma unroll
    for (int mf = 0; mf < 2; mf++) {
        int r0 = mw * 32 + mf * 16 + (lane >> 2);
        int r1 = r0 + 8;
        float d0 = EDGE ? sDst[r0] : 0.0f;
        float d1 = EDGE ? sDst[r1] : 0.0f;
#pragma unroll
        for (int nf = 0; nf < 8; nf++) {
            int c0 = nw * 64 + nf * 8 + (lane & 3) * 2;
            float* v = acc[mf][nf];
            float wl0 = EDGE ? sW1l[c0] : 0.0f;
            float wl1 = EDGE ? sW1l[c0 + 1] : 0.0f;
            float h00 = silu_f(v[0] + sB1[c0]     + d0 * wl0);
            float h01 = silu_f(v[1] + sB1[c0 + 1] + d0 * wl1);
            float h10 = silu_f(v[2] + sB1[c0]     + d1 * wl0);
            float h11 = silu_f(v[3] + sB1[c0 + 1] + d1 * wl1);
            *(half2*)(smc + r0 * APB + c0 * 2) = __floats2half2_rn(h00, h01);
            *(half2*)(smc + r1 * APB + c0 * 2) = __floats2half2_rn(h10, h11);
            v[0] = v[1] = v[2] = v[3] = 0.0f;
        }
    }
    // (first GEMM2 chunk's sync orders these writes)

    // GEMM2: K=128 (2 chunks)
    gemm_fp16(g_w2h, 2, smc, smbase, mw, nw, lane, tid, acc);

    // epilogue 2: stage fp32 result over the A tile region (h is dead now)
#pragma unroll
    for (int mf = 0; mf < 2; mf++) {
        int r0 = mw * 32 + mf * 16 + (lane >> 2);
        int r1 = r0 + 8;
#pragma unroll
        for (int nf = 0; nf < 8; nf++) {
            int c0 = nw * 64 + nf * 8 + (lane & 3) * 2;
            float* v = acc[mf][nf];
            float o00 = v[0] + sB2[c0];
            float o01 = v[1] + sB2[c0 + 1];
            float o10 = v[2] + sB2[c0];
            float o11 = v[3] + sB2[c0 + 1];
            if (EDGE) {
                o00 = silu_f(o00); o01 = silu_f(o01);
                o10 = silu_f(o10); o11 = silu_f(o11);
            }
            *(float2*)(smc + r0 * APB + c0 * 4) = make_float2(o00, o01);
            *(float2*)(smc + r1 * APB + c0 * 4) = make_float2(o10, o11);
        }
    }
    __syncthreads();

    // writeout: 128 rows x 2 halves, scatter-add or store
    {
        int r = tid >> 1, half = tid & 1;
        const float4* src = (const float4*)(smc + r * APB + half * 256);
        if (EDGE) {
            int rc = sRec[r];
            if (rc >= 0) {
                float* dst = &g_aggr[(size_t)rc * HDIM + half * 64];
#pragma unroll
                for (int j = 0; j < 16; j++) {
                    float4 v = src[j];
                    red4(dst + j * 4, v.x, v.y, v.z, v.w);
                }
            }
        } else {
            int gn = m0 + r;
            if (gn < M) {
                float4* dst = (float4*)&out[(size_t)gn * HDIM + half * 64];
#pragma unroll
                for (int j = 0; j < 16; j++) dst[j] = src[j];
            }
        }
    }
}

// ------------------------- launch -------------------------
extern "C" void kernel_launch(void* const* d_in, const int* in_sizes, int n_in,
                              void* d_out, int out_size) {
    const float* x   = (const float*)d_in[0];
    const float* pos = (const float*)d_in[1];
    const int*   ei  = (const int*)d_in[2];
    const float* mw1 = (const float*)d_in[3];
    const float* mb1 = (const float*)d_in[4];
    const float* mw2 = (const float*)d_in[5];
    const float* mb2 = (const float*)d_in[6];
    const float* uw1 = (const float*)d_in[7];
    const float* ub1 = (const float*)d_in[8];
    const float* uw2 = (const float*)d_in[9];
    const float* ub2 = (const float*)d_in[10];

    int N = in_sizes[0] / HDIM;
    int E = in_sizes[2] / 2;

    cudaFuncSetAttribute(mlp_mma_kernel<true>,
                         cudaFuncAttributeMaxDynamicSharedMemorySize, SMEM_BYTES);
    cudaFuncSetAttribute(mlp_mma_kernel<false>,
                         cudaFuncAttributeMaxDynamicSharedMemorySize, SMEM_BYTES);

    zero_kernel<<<256, 256>>>(N * HDIM);
    prep_kernel<<<512, 256>>>(ei, pos, N, E);
    wt_kernel<<<192, 256>>>(mw1, mw2);
    mlp_mma_kernel<true><<<(E + TMR - 1) / TMR, 256, SMEM_BYTES>>>(
        x, mw1, mb1, mb2, nullptr, E);
    wt_kernel<<<192, 256>>>(uw1, uw2);
    mlp_mma_kernel<false><<<(N + TMR - 1) / TMR, 256, SMEM_BYTES>>>(
        x, uw1, ub1, ub2, (float*)d_out, N);
}

// round 10
// speedup vs baseline: 2.2016x; 1.0289x over previous
#include <cuda_runtime.h>
#include <cuda_fp16.h>
#include <math.h>
#include <stdint.h>

#define HDIM 128
#define MAXN 50000
#define MAXE 640000
#define TMR  128                    // rows per CTA tile

// byte-offset shared layout
#define APB     528                 // A row pitch bytes (264 halves)
#define WB_B    (TMR * APB)         // 67584
#define WB_CHB  16384               // one 64k x 128n fp16 chunk, frag-ordered
#define B1_B    (WB_B + 2 * WB_CHB) // 100352
#define B2_B    (B1_B + 512)
#define W1L_B   (B2_B + 512)
#define DIST_B  (W1L_B + 512)
#define REC_B   (DIST_B + 512)
#define SEND_B  (REC_B + 512)
#define SMEM_BYTES (SEND_B + 512)   // 103424 -> 2 CTAs/SM

// ------------------------- device scratch -------------------------
__device__ __align__(16) float g_aggr[(size_t)MAXN * HDIM];
__device__ int   g_send[MAXE];
__device__ int   g_rec[MAXE];
__device__ float g_dist[MAXE];
// frag-ordered fp16 weights: [kchunk64][nb*4+ks][lane][reg] packed as halves
__device__ __align__(16) __half g_w1h[4 * 8192];   // K=256: 4 chunks
__device__ __align__(16) __half g_w2h[2 * 8192];   // K=128: 2 chunks

// ------------------------- helpers -------------------------
__device__ __forceinline__ float silu_f(float v) {
    return __fdividef(v, 1.0f + __expf(-v));
}
__device__ __forceinline__ uint32_t cvta_sh(const void* p) {
    uint32_t a;
    asm("{ .reg .u64 t; cvta.to.shared.u64 t, %1; cvt.u32.u64 %0, t; }"
        : "=r"(a) : "l"(p));
    return a;
}
__device__ __forceinline__ void mma16(float d[4], const uint32_t a[4],
                                      const uint32_t b[2]) {
    asm volatile(
        "mma.sync.aligned.m16n8k16.row.col.f32.f16.f16.f32 "
        "{%0,%1,%2,%3},{%4,%5,%6,%7},{%8,%9},{%0,%1,%2,%3};"
        : "+f"(d[0]), "+f"(d[1]), "+f"(d[2]), "+f"(d[3])
        : "r"(a[0]), "r"(a[1]), "r"(a[2]), "r"(a[3]), "r"(b[0]), "r"(b[1]));
}
__device__ __forceinline__ void ldsm4(uint32_t r[4], uint32_t addr) {
    asm volatile("ldmatrix.sync.aligned.m8n8.x4.shared.b16 {%0,%1,%2,%3}, [%4];"
                 : "=r"(r[0]), "=r"(r[1]), "=r"(r[2]), "=r"(r[3]) : "r"(addr));
}
__device__ __forceinline__ void red4(float* p, float a, float b, float c, float d) {
    asm volatile("red.global.add.v4.f32 [%0], {%1,%2,%3,%4};"
                 :: "l"(p), "f"(a), "f"(b), "f"(c), "f"(d) : "memory");
}
__device__ __forceinline__ void cp16(uint32_t dst_sh, const void* src) {
    asm volatile("cp.async.ca.shared.global [%0], [%1], 16;"
                 :: "r"(dst_sh), "l"(src) : "memory");
}
__device__ __forceinline__ void cp_commit() {
    asm volatile("cp.async.commit_group;" ::: "memory");
}
template <int W>
__device__ __forceinline__ void cp_wait() {
    asm volatile("cp.async.wait_group %0;" :: "n"(W) : "memory");
}

// ------------------------- prep kernels -------------------------
__global__ void zero_kernel(int n) {
    int i = blockIdx.x * blockDim.x + threadIdx.x;
    int st = gridDim.x * blockDim.x;
    for (; i < n; i += st) g_aggr[i] = 0.0f;
}

__global__ void prep_kernel(const int* __restrict__ ei32,
                            const float* __restrict__ pos, int N, int E) {
    bool is64 = true;
#pragma unroll
    for (int t = 0; t < 16; t++) is64 &= (ei32[2 * t + 1] == 0);
    int i = blockIdx.x * blockDim.x + threadIdx.x;
    int st = gridDim.x * blockDim.x;
    for (; i < E; i += st) {
        int s, r;
        if (is64) { s = ei32[2 * (size_t)i]; r = ei32[2 * ((size_t)E + i)]; }
        else      { s = ei32[i];             r = ei32[(size_t)E + i]; }
        s = min(max(s, 0), N - 1);
        r = min(max(r, 0), N - 1);
        g_send[i] = s;
        g_rec[i]  = r;
        float dx = pos[s * 3 + 0] - pos[r * 3 + 0];
        float dy = pos[s * 3 + 1] - pos[r * 3 + 1];
        float dz = pos[s * 3 + 2] - pos[r * 3 + 2];
        g_dist[i] = sqrtf(dx * dx + dy * dy + dz * dz);
    }
}

// frag-order half-index for weight element (n, k), 64k-chunks.
// word = chunkbase + (nb*4+ks)*64 + lane*2 + reg
__device__ __forceinline__ int fragh(int n, int k) {
    int kc   = k >> 6;
    int ks   = (k >> 4) & 3;
    int reg  = (k >> 3) & 1;
    int lane = (n & 7) * 4 + ((k >> 1) & 3);
    int idx32 = kc * 4096 + (((n >> 3) * 4 + ks) << 6) + lane * 2 + reg;
    return idx32 * 2 + (k & 1);
}

// transpose+permute weights to fp16 frag order
__global__ void wt_kernel(const float* __restrict__ w1, const float* __restrict__ w2) {
    int i = blockIdx.x * blockDim.x + threadIdx.x;
    int st = gridDim.x * blockDim.x;
    for (; i < 128 * 256 + 128 * 128; i += st) {
        if (i < 128 * 256) {
            int n = i >> 8, k = i & 255;
            g_w1h[fragh(n, k)] = __float2half_rn(w1[k * 128 + n]);
        } else {
            int j = i - 128 * 256;
            int n = j >> 7, k = j & 127;
            g_w2h[fragh(n, k)] = __float2half_rn(w2[k * 128 + n]);
        }
    }
}

// ------------------------- fp16 mma GEMMs (32x64 warp tiles, 8 warps) --------
__device__ __forceinline__ void issueB1(const __half* __restrict__ gB, int c,
                                        int buf, uint32_t smbase, int tid) {
#pragma unroll
    for (int it = 0; it < 4; it++) {
        int idx = (tid + it * 256) * 16;
        cp16(smbase + WB_B + buf * WB_CHB + idx, (const char*)gB + c * WB_CHB + idx);
    }
}
__device__ __forceinline__ void issueW2(const __half* __restrict__ gB,
                                        uint32_t smbase, int tid) {
#pragma unroll
    for (int it = 0; it < 8; it++) {
        int idx = (tid + it * 256) * 16;
        cp16(smbase + WB_B + idx, (const char*)gB + idx);
    }
}

// per-thread ldmatrix A base row address (mf=0), koff folded in
__device__ __forceinline__ uint32_t a_addr(uint32_t smbase, int mw, int lane) {
    int row  = mw * 32 + (lane & 7) + ((lane >> 3) & 1) * 8;
    int koff = (lane >> 4) * 8;           // halves
    return smbase + row * APB + koff * 2;
}

__device__ __forceinline__ void gemm1(const __half* __restrict__ gB,
                                      char* smc, uint32_t smbase,
                                      int mw, int nw, int lane, int tid,
                                      float acc[2][8][4]) {
    issueB1(gB, 0, 0, smbase, tid);
    cp_commit();
    const uint32_t abase = a_addr(smbase, mw, lane);
    for (int c = 0; c < 4; c++) {
        if (c + 1 < 4) {
            issueB1(gB, c + 1, (c + 1) & 1, smbase, tid);
            cp_commit();
            cp_wait<1>();
        } else {
            cp_wait<0>();
        }
        __syncthreads();   // chunk c visible; orders prior sA writes
        const char* wb = smc + WB_B + (c & 1) * WB_CHB;
#pragma unroll
        for (int ks = 0; ks < 4; ks++) {
            uint32_t a[2][4];
            uint2    b[8];
#pragma unroll
            for (int mf = 0; mf < 2; mf++)
                ldsm4(a[mf], abase + mf * 16 * APB + (c * 64 + ks * 16) * 2);
#pragma unroll
            for (int nf = 0; nf < 8; nf++) {
                int nb = nw * 8 + nf;
                b[nf] = *(const uint2*)(wb + (((nb * 4 + ks) << 5) + lane) * 8);
            }
#pragma unroll
            for (int mf = 0; mf < 2; mf++)
#pragma unroll
                for (int nf = 0; nf < 8; nf++)
                    mma16(acc[mf][nf], a[mf], (const uint32_t*)&b[nf]);
        }
        __syncthreads();   // reads done before buf refill / sA mutation
    }
}

// GEMM2: whole K=128 in one 32KB frag buffer, no internal barriers
__device__ __forceinline__ void gemm2(char* smc, uint32_t smbase,
                                      int mw, int nw, int lane,
                                      float acc[2][8][4]) {
    const uint32_t abase = a_addr(smbase, mw, lane);
#pragma unroll
    for (int ks8 = 0; ks8 < 8; ks8++) {
        const char* wb = smc + WB_B + (ks8 >> 2) * WB_CHB;
        int ks = ks8 & 3;
        uint32_t a[2][4];
        uint2    b[8];
#pragma unroll
        for (int mf = 0; mf < 2; mf++)
            ldsm4(a[mf], abase + mf * 16 * APB + (ks8 * 16) * 2);
#pragma unroll
        for (int nf = 0; nf < 8; nf++) {
            int nb = nw * 8 + nf;
            b[nf] = *(const uint2*)(wb + (((nb * 4 + ks) << 5) + lane) * 8);
        }
#pragma unroll
        for (int mf = 0; mf < 2; mf++)
#pragma unroll
            for (int nf = 0; nf < 8; nf++)
                mma16(acc[mf][nf], a[mf], (const uint32_t*)&b[nf]);
    }
}

// ------------------------- fused MLP kernel (edge / node) -------------------------
template <bool EDGE>
__global__ void __launch_bounds__(256, 2) mlp_mma_kernel(
    const float* __restrict__ x,
    const float* __restrict__ w1full,   // original w1 (dist row, edge only)
    const float* __restrict__ b1, const float* __restrict__ b2,
    float* __restrict__ out, int M) {
    extern __shared__ char smc[];
    const uint32_t smbase = cvta_sh(smc);
    float* sB1  = (float*)(smc + B1_B);
    float* sB2  = (float*)(smc + B2_B);
    float* sW1l = (float*)(smc + W1L_B);
    float* sDst = (float*)(smc + DIST_B);
    int*   sRec = (int*)(smc + REC_B);
    int*   sSnd = (int*)(smc + SEND_B);

    const int tid  = threadIdx.x;
    const int lane = tid & 31;
    const int wid  = tid >> 5;
    const int mw   = wid >> 1;   // 0..3 (32-row block)
    const int nw   = wid & 1;    // 0..1 (64-col block)
    const int m0   = blockIdx.x * TMR;

    if (tid < 128) {
        sB1[tid] = b1[tid];
        sB2[tid] = b2[tid];
        if (EDGE) {
            sW1l[tid] = w1full[(size_t)256 * 128 + tid];
            int ge = m0 + tid;
            if (ge < M) {
                sSnd[tid] = g_send[ge];
                sRec[tid] = g_rec[ge];
                sDst[tid] = g_dist[ge];
            } else {
                sSnd[tid] = 0; sRec[tid] = -1; sDst[tid] = 0.0f;
            }
        }
    }
    __syncthreads();

    // gather state rows -> fp16: cols 0..127 (send/x) / 128..255 (rec/aggr)
    const float4* x4 = (const float4*)x;
    const float4* a4 = (const float4*)g_aggr;
    for (int i = tid; i < TMR * 32; i += 256) {
        int r = i >> 5, f = i & 31;
        float4 v0, v1;
        if (EDGE) {
            int s  = sSnd[r];
            int rc = sRec[r];
            if (rc < 0) rc = 0;
            v0 = x4[(size_t)s * 32 + f];
            v1 = x4[(size_t)rc * 32 + f];
        } else {
            int gn = m0 + r;
            if (gn >= M) gn = M - 1;
            v0 = x4[(size_t)gn * 32 + f];
            v1 = a4[(size_t)gn * 32 + f];
        }
        uint2 u0, u1;
        ((half2*)&u0)[0] = __floats2half2_rn(v0.x, v0.y);
        ((half2*)&u0)[1] = __floats2half2_rn(v0.z, v0.w);
        ((half2*)&u1)[0] = __floats2half2_rn(v1.x, v1.y);
        ((half2*)&u1)[1] = __floats2half2_rn(v1.z, v1.w);
        *(uint2*)(smc + r * APB + f * 8)       = u0;
        *(uint2*)(smc + r * APB + 256 + f * 8) = u1;
    }
    // (first gemm chunk's sync orders the gather)

    float acc[2][8][4];
#pragma unroll
    for (int mf = 0; mf < 2; mf++)
#pragma unroll
        for (int nf = 0; nf < 8; nf++)
#pragma unroll
            for (int g = 0; g < 4; g++) acc[mf][nf][g] = 0.0f;

    // GEMM1: K=256 (4 chunks of 64)
    gemm1(g_w1h, smc, smbase, mw, nw, lane, tid, acc);

    // prefetch ALL of w2 (32KB) while we do epilogue math
    issueW2(g_w2h, smbase, tid);
    cp_commit();

    // epilogue 1: h = silu(acc + b1 [+ dist*w1_last]) -> fp16 -> A cols 0..127
#pragma unroll
    for (int mf = 0; mf < 2; mf++) {
        int r0 = mw * 32 + mf * 16 + (lane >> 2);
        int r1 = r0 + 8;
        float d0 = EDGE ? sDst[r0] : 0.0f;
        float d1 = EDGE ? sDst[r1] : 0.0f;
#pragma unroll
        for (int nf = 0; nf < 8; nf++) {
            int c0 = nw * 64 + nf * 8 + (lane & 3) * 2;
            float* v = acc[mf][nf];
            float wl0 = EDGE ? sW1l[c0] : 0.0f;
            float wl1 = EDGE ? sW1l[c0 + 1] : 0.0f;
            float h00 = silu_f(v[0] + sB1[c0]     + d0 * wl0);
            float h01 = silu_f(v[1] + sB1[c0 + 1] + d0 * wl1);
            float h10 = silu_f(v[2] + sB1[c0]     + d1 * wl0);
            float h11 = silu_f(v[3] + sB1[c0 + 1] + d1 * wl1);
            *(half2*)(smc + r0 * APB + c0 * 2) = __floats2half2_rn(h00, h01);
            *(half2*)(smc + r1 * APB + c0 * 2) = __floats2half2_rn(h10, h11);
            v[0] = v[1] = v[2] = v[3] = 0.0f;
        }
    }
    cp_wait<0>();
    __syncthreads();   // w2 + h tiles visible to all

    // GEMM2: K=128, un-barriered
    gemm2(smc, smbase, mw, nw, lane, acc);
    __syncthreads();   // all A reads done before fp32 overlay

    // epilogue 2: stage fp32 result over the A tile region (h is dead now)
#pragma unroll
    for (int mf = 0; mf < 2; mf++) {
        int r0 = mw * 32 + mf * 16 + (lane >> 2);
        int r1 = r0 + 8;
#pragma unroll
        for (int nf = 0; nf < 8; nf++) {
            int c0 = nw * 64 + nf * 8 + (lane & 3) * 2;
            float* v = acc[mf][nf];
            float o00 = v[0] + sB2[c0];
            float o01 = v[1] + sB2[c0 + 1];
            float o10 = v[2] + sB2[c0];
            float o11 = v[3] + sB2[c0 + 1];
            if (EDGE) {
                o00 = silu_f(o00); o01 = silu_f(o01);
                o10 = silu_f(o10); o11 = silu_f(o11);
            }
            *(float2*)(smc + r0 * APB + c0 * 4) = make_float2(o00, o01);
            *(float2*)(smc + r1 * APB + c0 * 4) = make_float2(o10, o11);
        }
    }
    __syncthreads();

    // writeout: 128 rows x 2 halves, scatter-add or store
    {
        int r = tid >> 1, half = tid & 1;
        const float4* src = (const float4*)(smc + r * APB + half * 256);
        if (EDGE) {
            int rc = sRec[r];
            if (rc >= 0) {
                float* dst = &g_aggr[(size_t)rc * HDIM + half * 64];
#pragma unroll
                for (int j = 0; j < 16; j++) {
                    float4 v = src[j];
                    red4(dst + j * 4, v.x, v.y, v.z, v.w);
                }
            }
        } else {
            int gn = m0 + r;
            if (gn < M) {
                float4* dst = (float4*)&out[(size_t)gn * HDIM + half * 64];
#pragma unroll
                for (int j = 0; j < 16; j++) dst[j] = src[j];
            }
        }
    }
}

// ------------------------- launch -------------------------
extern "C" void kernel_launch(void* const* d_in, const int* in_sizes, int n_in,
                              void* d_out, int out_size) {
    const float* x   = (const float*)d_in[0];
    const float* pos = (const float*)d_in[1];
    const int*   ei  = (const int*)d_in[2];
    const float* mw1 = (const float*)d_in[3];
    const float* mb1 = (const float*)d_in[4];
    const float* mw2 = (const float*)d_in[5];
    const float* mb2 = (const float*)d_in[6];
    const float* uw1 = (const float*)d_in[7];
    const float* ub1 = (const float*)d_in[8];
    const float* uw2 = (const float*)d_in[9];
    const float* ub2 = (const float*)d_in[10];

    int N = in_sizes[0] / HDIM;
    int E = in_sizes[2] / 2;

    cudaFuncSetAttribute(mlp_mma_kernel<true>,
                         cudaFuncAttributeMaxDynamicSharedMemorySize, SMEM_BYTES);
    cudaFuncSetAttribute(mlp_mma_kernel<false>,
                         cudaFuncAttributeMaxDynamicSharedMemorySize, SMEM_BYTES);

    zero_kernel<<<256, 256>>>(N * HDIM);
    prep_kernel<<<512, 256>>>(ei, pos, N, E);
    wt_kernel<<<192, 256>>>(mw1, mw2);
    mlp_mma_kernel<true><<<(E + TMR - 1) / TMR, 256, SMEM_BYTES>>>(
        x, mw1, mb1, mb2, nullptr, E);
    wt_kernel<<<192, 256>>>(uw1, uw2);
    mlp_mma_kernel<false><<<(N + TMR - 1) / TMR, 256, SMEM_BYTES>>>(
        x, uw1, ub1, ub2, (float*)d_out, N);
}

// round 11
// speedup vs baseline: 2.3514x; 1.0680x over previous
#include <cuda_runtime.h>
#include <cuda_fp16.h>
#include <math.h>
#include <stdint.h>

#define HDIM 128
#define MAXN 50000
#define MAXE 640000
#define TMR  128                    // rows per CTA tile

// byte-offset shared layout
#define APB     528                 // A row pitch bytes (264 halves)
#define WB_B    (TMR * APB)         // 67584
#define WB_CHB  16384               // one 64k x 128n fp16 chunk, frag-ordered
#define B1_B    (WB_B + 2 * WB_CHB) // 100352
#define B2_B    (B1_B + 512)
#define W1L_B   (B2_B + 512)
#define DIST_B  (W1L_B + 512)
#define REC_B   (DIST_B + 512)
#define SEND_B  (REC_B + 512)
#define SMEM_BYTES (SEND_B + 512)   // 103424 -> 2 CTAs/SM

// ------------------------- device scratch -------------------------
__device__ __align__(16) float  g_aggr[(size_t)MAXN * HDIM];
__device__ __align__(16) __half g_x16[(size_t)MAXN * HDIM];
__device__ int   g_send[MAXE];
__device__ int   g_rec[MAXE];
__device__ float g_dist[MAXE];
// frag-ordered fp16 weights: [kchunk64][nb*4+ks][lane][reg] packed as halves
__device__ __align__(16) __half g_w1h[4 * 8192];   // edge w1, K=256
__device__ __align__(16) __half g_w2h[2 * 8192];   // edge w2, K=128
__device__ __align__(16) __half g_u1h[4 * 8192];   // node w1, K=256
__device__ __align__(16) __half g_u2h[2 * 8192];   // node w2, K=128

// ------------------------- helpers -------------------------
__device__ __forceinline__ float silu_f(float v) {
    return __fdividef(v, 1.0f + __expf(-v));
}
__device__ __forceinline__ uint32_t cvta_sh(const void* p) {
    uint32_t a;
    asm("{ .reg .u64 t; cvta.to.shared.u64 t, %1; cvt.u32.u64 %0, t; }"
        : "=r"(a) : "l"(p));
    return a;
}
__device__ __forceinline__ void mma16(float d[4], const uint32_t a[4],
                                      const uint32_t b[2]) {
    asm volatile(
        "mma.sync.aligned.m16n8k16.row.col.f32.f16.f16.f32 "
        "{%0,%1,%2,%3},{%4,%5,%6,%7},{%8,%9},{%0,%1,%2,%3};"
        : "+f"(d[0]), "+f"(d[1]), "+f"(d[2]), "+f"(d[3])
        : "r"(a[0]), "r"(a[1]), "r"(a[2]), "r"(a[3]), "r"(b[0]), "r"(b[1]));
}
__device__ __forceinline__ void ldsm4(uint32_t r[4], uint32_t addr) {
    asm volatile("ldmatrix.sync.aligned.m8n8.x4.shared.b16 {%0,%1,%2,%3}, [%4];"
                 : "=r"(r[0]), "=r"(r[1]), "=r"(r[2]), "=r"(r[3]) : "r"(addr));
}
__device__ __forceinline__ void red4(float* p, float a, float b, float c, float d) {
    asm volatile("red.global.add.v4.f32 [%0], {%1,%2,%3,%4};"
                 :: "l"(p), "f"(a), "f"(b), "f"(c), "f"(d) : "memory");
}
__device__ __forceinline__ void cp16(uint32_t dst_sh, const void* src) {
    asm volatile("cp.async.ca.shared.global [%0], [%1], 16;"
                 :: "r"(dst_sh), "l"(src) : "memory");
}
__device__ __forceinline__ void cp_commit() {
    asm volatile("cp.async.commit_group;" ::: "memory");
}
template <int W>
__device__ __forceinline__ void cp_wait() {
    asm volatile("cp.async.wait_group %0;" :: "n"(W) : "memory");
}

// frag-order half-index for weight element (n, k), 64k-chunks.
// word = chunkbase + (nb*4+ks)*64 + lane*2 + reg
__device__ __forceinline__ int fragh(int n, int k) {
    int kc   = k >> 6;
    int ks   = (k >> 4) & 3;
    int reg  = (k >> 3) & 1;
    int lane = (n & 7) * 4 + ((k >> 1) & 3);
    int idx32 = kc * 4096 + (((n >> 3) * 4 + ks) << 6) + lane * 2 + reg;
    return idx32 * 2 + (k & 1);
}

// ------------------------- fused prep kernel -------------------------
// jobs: zero aggr | x->fp16 | edge decode+dist | 4x weight transposes
__global__ void prep_all(const int* __restrict__ ei32,
                         const float* __restrict__ pos,
                         const float* __restrict__ x,
                         const float* __restrict__ mw1, const float* __restrict__ mw2,
                         const float* __restrict__ uw1, const float* __restrict__ uw2,
                         int N, int E) {
    bool is64 = true;
#pragma unroll
    for (int t = 0; t < 16; t++) is64 &= (ei32[2 * t + 1] == 0);

    const long long NH = (long long)N * HDIM;
    const long long t0 = NH;                 // zero aggr
    const long long t1 = t0 + NH;            // x -> fp16
    const long long t2 = t1 + E;             // edges
    const long long t3 = t2 + 32768;         // edge w1
    const long long t4 = t3 + 16384;         // edge w2
    const long long t5 = t4 + 32768;         // node w1
    const long long t6 = t5 + 16384;         // node w2

    long long i = (long long)blockIdx.x * blockDim.x + threadIdx.x;
    long long st = (long long)gridDim.x * blockDim.x;
    for (; i < t6; i += st) {
        if (i < t0) {
            g_aggr[i] = 0.0f;
        } else if (i < t1) {
            long long j = i - t0;
            g_x16[j] = __float2half_rn(x[j]);
        } else if (i < t2) {
            int e = (int)(i - t1);
            int s, r;
            if (is64) { s = ei32[2 * (size_t)e]; r = ei32[2 * ((size_t)E + e)]; }
            else      { s = ei32[e];             r = ei32[(size_t)E + e]; }
            s = min(max(s, 0), N - 1);
            r = min(max(r, 0), N - 1);
            g_send[e] = s;
            g_rec[e]  = r;
            float dx = pos[s * 3 + 0] - pos[r * 3 + 0];
            float dy = pos[s * 3 + 1] - pos[r * 3 + 1];
            float dz = pos[s * 3 + 2] - pos[r * 3 + 2];
            g_dist[e] = sqrtf(dx * dx + dy * dy + dz * dz);
        } else if (i < t3) {
            int j = (int)(i - t2);
            int n = j >> 8, k = j & 255;
            g_w1h[fragh(n, k)] = __float2half_rn(mw1[k * 128 + n]);
        } else if (i < t4) {
            int j = (int)(i - t3);
            int n = j >> 7, k = j & 127;
            g_w2h[fragh(n, k)] = __float2half_rn(mw2[k * 128 + n]);
        } else if (i < t5) {
            int j = (int)(i - t4);
            int n = j >> 8, k = j & 255;
            g_u1h[fragh(n, k)] = __float2half_rn(uw1[k * 128 + n]);
        } else {
            int j = (int)(i - t5);
            int n = j >> 7, k = j & 127;
            g_u2h[fragh(n, k)] = __float2half_rn(uw2[k * 128 + n]);
        }
    }
}

// ------------------------- fp16 mma GEMMs (32x64 warp tiles, 8 warps) --------
__device__ __forceinline__ void issueB1(const __half* __restrict__ gB, int c,
                                        int buf, uint32_t smbase, int tid) {
#pragma unroll
    for (int it = 0; it < 4; it++) {
        int idx = (tid + it * 256) * 16;
        cp16(smbase + WB_B + buf * WB_CHB + idx, (const char*)gB + c * WB_CHB + idx);
    }
}
__device__ __forceinline__ void issueW2(const __half* __restrict__ gB,
                                        uint32_t smbase, int tid) {
#pragma unroll
    for (int it = 0; it < 8; it++) {
        int idx = (tid + it * 256) * 16;
        cp16(smbase + WB_B + idx, (const char*)gB + idx);
    }
}

// per-thread ldmatrix A base row address (mf=0), koff folded in
__device__ __forceinline__ uint32_t a_addr(uint32_t smbase, int mw, int lane) {
    int row  = mw * 32 + (lane & 7) + ((lane >> 3) & 1) * 8;
    int koff = (lane >> 4) * 8;           // halves
    return smbase + row * APB + koff * 2;
}

// Single barrier per chunk: cp for c+1 issued AFTER bar(c), so buffer
// (c+1)&1's readers (chunk c-1) are provably done. Caller must __syncthreads()
// after return before mutating sA or WB.
__device__ __forceinline__ void gemm1(const __half* __restrict__ gB,
                                      char* smc, uint32_t smbase,
                                      int mw, int nw, int lane, int tid,
                                      float acc[2][8][4]) {
    issueB1(gB, 0, 0, smbase, tid);
    cp_commit();
    const uint32_t abase = a_addr(smbase, mw, lane);
    for (int c = 0; c < 4; c++) {
        cp_wait<0>();
        __syncthreads();   // chunk c visible to all; chunk c-1 reads all done
        if (c + 1 < 4) {
            issueB1(gB, c + 1, (c + 1) & 1, smbase, tid);
            cp_commit();
        }
        const char* wb = smc + WB_B + (c & 1) * WB_CHB;
#pragma unroll
        for (int ks = 0; ks < 4; ks++) {
            uint32_t a[2][4];
            uint2    b[8];
#pragma unroll
            for (int mf = 0; mf < 2; mf++)
                ldsm4(a[mf], abase + mf * 16 * APB + (c * 64 + ks * 16) * 2);
#pragma unroll
            for (int nf = 0; nf < 8; nf++) {
                int nb = nw * 8 + nf;
                b[nf] = *(const uint2*)(wb + (((nb * 4 + ks) << 5) + lane) * 8);
            }
#pragma unroll
            for (int mf = 0; mf < 2; mf++)
#pragma unroll
                for (int nf = 0; nf < 8; nf++)
                    mma16(acc[mf][nf], a[mf], (const uint32_t*)&b[nf]);
        }
    }
}

// GEMM2: whole K=128 in one 32KB frag buffer, no internal barriers
__device__ __forceinline__ void gemm2(char* smc, uint32_t smbase,
                                      int mw, int nw, int lane,
                                      float acc[2][8][4]) {
    const uint32_t abase = a_addr(smbase, mw, lane);
#pragma unroll
    for (int ks8 = 0; ks8 < 8; ks8++) {
        const char* wb = smc + WB_B + (ks8 >> 2) * WB_CHB;
        int ks = ks8 & 3;
        uint32_t a[2][4];
        uint2    b[8];
#pragma unroll
        for (int mf = 0; mf < 2; mf++)
            ldsm4(a[mf], abase + mf * 16 * APB + (ks8 * 16) * 2);
#pragma unroll
        for (int nf = 0; nf < 8; nf++) {
            int nb = nw * 8 + nf;
            b[nf] = *(const uint2*)(wb + (((nb * 4 + ks) << 5) + lane) * 8);
        }
#pragma unroll
        for (int mf = 0; mf < 2; mf++)
#pragma unroll
            for (int nf = 0; nf < 8; nf++)
                mma16(acc[mf][nf], a[mf], (const uint32_t*)&b[nf]);
    }
}

// ------------------------- fused MLP kernel (edge / node) -------------------------
template <bool EDGE>
__global__ void __launch_bounds__(256, 2) mlp_mma_kernel(
    const float* __restrict__ w1full,   // original w1 (dist row, edge only)
    const float* __restrict__ b1, const float* __restrict__ b2,
    float* __restrict__ out, int M) {
    extern __shared__ char smc[];
    const uint32_t smbase = cvta_sh(smc);
    float* sB1  = (float*)(smc + B1_B);
    float* sB2  = (float*)(smc + B2_B);
    float* sW1l = (float*)(smc + W1L_B);
    float* sDst = (float*)(smc + DIST_B);
    int*   sRec = (int*)(smc + REC_B);
    int*   sSnd = (int*)(smc + SEND_B);

    const __half* gw1 = EDGE ? g_w1h : g_u1h;
    const __half* gw2 = EDGE ? g_w2h : g_u2h;

    const int tid  = threadIdx.x;
    const int lane = tid & 31;
    const int wid  = tid >> 5;
    const int mw   = wid >> 1;   // 0..3 (32-row block)
    const int nw   = wid & 1;    // 0..1 (64-col block)
    const int m0   = blockIdx.x * TMR;

    if (tid < 128) {
        sB1[tid] = b1[tid];
        sB2[tid] = b2[tid];
        if (EDGE) {
            sW1l[tid] = w1full[(size_t)256 * 128 + tid];
            int ge = m0 + tid;
            if (ge < M) {
                sSnd[tid] = g_send[ge];
                sRec[tid] = g_rec[ge];
                sDst[tid] = g_dist[ge];
            } else {
                sSnd[tid] = 0; sRec[tid] = -1; sDst[tid] = 0.0f;
            }
        }
    }
    __syncthreads();

    // gather state rows: cols 0..127 from x16 (pure copy); 128..255 from
    // x16 (edge) or aggr fp32->fp16 (node)
    const uint4* x16 = (const uint4*)g_x16;   // 16 uint4 per row
    for (int i = tid; i < TMR * 16; i += 256) {
        int r = i >> 4, c = i & 15;
        if (EDGE) {
            int s  = sSnd[r];
            int rc = sRec[r];
            if (rc < 0) rc = 0;
            uint4 vs = x16[(size_t)s * 16 + c];
            uint4 vr = x16[(size_t)rc * 16 + c];
            *(uint4*)(smc + r * APB + c * 16)       = vs;
            *(uint4*)(smc + r * APB + 256 + c * 16) = vr;
        } else {
            int gn = m0 + r;
            if (gn >= M) gn = M - 1;
            uint4 vx = x16[(size_t)gn * 16 + c];
            *(uint4*)(smc + r * APB + c * 16) = vx;
            const float4* ar = (const float4*)&g_aggr[(size_t)gn * HDIM + c * 8];
            float4 a0 = ar[0], a1 = ar[1];
            uint4 u;
            ((half2*)&u)[0] = __floats2half2_rn(a0.x, a0.y);
            ((half2*)&u)[1] = __floats2half2_rn(a0.z, a0.w);
            ((half2*)&u)[2] = __floats2half2_rn(a1.x, a1.y);
            ((half2*)&u)[3] = __floats2half2_rn(a1.z, a1.w);
            *(uint4*)(smc + r * APB + 256 + c * 16) = u;
        }
    }
    // (first gemm chunk's bar orders the gather)

    float acc[2][8][4];
#pragma unroll
    for (int mf = 0; mf < 2; mf++)
#pragma unroll
        for (int nf = 0; nf < 8; nf++)
#pragma unroll
            for (int g = 0; g < 4; g++) acc[mf][nf][g] = 0.0f;

    // GEMM1: K=256 (4 chunks of 64)
    gemm1(gw1, smc, smbase, mw, nw, lane, tid, acc);
    __syncthreads();   // all chunk-3 reads (sA + WB) done

    // prefetch ALL of w2 (32KB) while we do epilogue math
    issueW2(gw2, smbase, tid);
    cp_commit();

    // epilogue 1: h = silu(acc + b1 [+ dist*w1_last]) -> fp16 -> A cols 0..127
#pragma unroll
    for (int mf = 0; mf < 2; mf++) {
        int r0 = mw * 32 + mf * 16 + (lane >> 2);
        int r1 = r0 + 8;
        float d0 = EDGE ? sDst[r0] : 0.0f;
        float d1 = EDGE ? sDst[r1] : 0.0f;
#pragma unroll
        for (int nf = 0; nf < 8; nf++) {
            int c0 = nw * 64 + nf * 8 + (lane & 3) * 2;
            float* v = acc[mf][nf];
            float wl0 = EDGE ? sW1l[c0] : 0.0f;
            float wl1 = EDGE ? sW1l[c0 + 1] : 0.0f;
            float h00 = silu_f(v[0] + sB1[c0]     + d0 * wl0);
            float h01 = silu_f(v[1] + sB1[c0 + 1] + d0 * wl1);
            float h10 = silu_f(v[2] + sB1[c0]     + d1 * wl0);
            float h11 = silu_f(v[3] + sB1[c0 + 1] + d1 * wl1);
            *(half2*)(smc + r0 * APB + c0 * 2) = __floats2half2_rn(h00, h01);
            *(half2*)(smc + r1 * APB + c0 * 2) = __floats2half2_rn(h10, h11);
            v[0] = v[1] = v[2] = v[3] = 0.0f;
        }
    }
    cp_wait<0>();
    __syncthreads();   // w2 + h tiles visible to all

    // GEMM2: K=128, un-barriered
    gemm2(smc, smbase, mw, nw, lane, acc);
    __syncthreads();   // all A reads done before fp32 overlay

    // epilogue 2: stage fp32 result over the A tile region (h is dead now)
#pragma unroll
    for (int mf = 0; mf < 2; mf++) {
        int r0 = mw * 32 + mf * 16 + (lane >> 2);
        int r1 = r0 + 8;
#pragma unroll
        for (int nf = 0; nf < 8; nf++) {
            int c0 = nw * 64 + nf * 8 + (lane & 3) * 2;
            float* v = acc[mf][nf];
            float o00 = v[0] + sB2[c0];
            float o01 = v[1] + sB2[c0 + 1];
            float o10 = v[2] + sB2[c0];
            float o11 = v[3] + sB2[c0 + 1];
            if (EDGE) {
                o00 = silu_f(o00); o01 = silu_f(o01);
                o10 = silu_f(o10); o11 = silu_f(o11);
            }
            *(float2*)(smc + r0 * APB + c0 * 4) = make_float2(o00, o01);
            *(float2*)(smc + r1 * APB + c0 * 4) = make_float2(o10, o11);
        }
    }
    __syncthreads();

    // writeout: 128 rows x 2 halves, scatter-add or store
    {
        int r = tid >> 1, half = tid & 1;
        const float4* src = (const float4*)(smc + r * APB + half * 256);
        if (EDGE) {
            int rc = sRec[r];
            if (rc >= 0) {
                float* dst = &g_aggr[(size_t)rc * HDIM + half * 64];
#pragma unroll
                for (int j = 0; j < 16; j++) {
                    float4 v = src[j];
                    red4(dst + j * 4, v.x, v.y, v.z, v.w);
                }
            }
        } else {
            int gn = m0 + r;
            if (gn < M) {
                float4* dst = (float4*)&out[(size_t)gn * HDIM + half * 64];
#pragma unroll
                for (int j = 0; j < 16; j++) dst[j] = src[j];
            }
        }
    }
}

// ------------------------- launch -------------------------
extern "C" void kernel_launch(void* const* d_in, const int* in_sizes, int n_in,
                              void* d_out, int out_size) {
    const float* x   = (const float*)d_in[0];
    const float* pos = (const float*)d_in[1];
    const int*   ei  = (const int*)d_in[2];
    const float* mw1 = (const float*)d_in[3];
    const float* mb1 = (const float*)d_in[4];
    const float* mw2 = (const float*)d_in[5];
    const float* mb2 = (const float*)d_in[6];
    const float* uw1 = (const float*)d_in[7];
    const float* ub1 = (const float*)d_in[8];
    const float* uw2 = (const float*)d_in[9];
    const float* ub2 = (const float*)d_in[10];

    int N = in_sizes[0] / HDIM;
    int E = in_sizes[2] / 2;

    cudaFuncSetAttribute(mlp_mma_kernel<true>,
                         cudaFuncAttributeMaxDynamicSharedMemorySize, SMEM_BYTES);
    cudaFuncSetAttribute(mlp_mma_kernel<false>,
                         cudaFuncAttributeMaxDynamicSharedMemorySize, SMEM_BYTES);

    prep_all<<<2048, 256>>>(ei, pos, x, mw1, mw2, uw1, uw2, N, E);
    mlp_mma_kernel<true><<<(E + TMR - 1) / TMR, 256, SMEM_BYTES>>>(
        mw1, mb1, mb2, nullptr, E);
    mlp_mma_kernel<false><<<(N + TMR - 1) / TMR, 256, SMEM_BYTES>>>(
        uw1, ub1, ub2, (float*)d_out, N);
}